// round 5
// baseline (speedup 1.0000x reference)
#include <cuda_runtime.h>
#include <cuda_bf16.h>
#include <cstdint>

#define NTOK 16384
#define DIM  512
#define NEXP 8
#define HID  1024
#define NSLOT (NTOK*2)
#define MAXTILES (NSLOT/128 + NEXP)   // 264

// ---------------- device-global scratch (no allocs allowed) ----------------
__device__ float g_probsum[NEXP];
__device__ int   g_count[NEXP];
__device__ int   g_cursor[NEXP];
__device__ int   g_off[NEXP+1];
__device__ int   g_tile_e[MAXTILES];
__device__ int   g_tile_r0[MAXTILES];
__device__ int   g_tile_cnt[MAXTILES];
__device__ int   g_ntiles;
__device__ int   g_tok[NSLOT];
__device__ int   g_eidx[NTOK*2];
__device__ int   g_slot[NTOK*2];
__device__ float g_w[NTOK*2];

__device__ __nv_bfloat16 g_xhi[(size_t)NTOK*DIM];
__device__ __nv_bfloat16 g_xlo[(size_t)NTOK*DIM];
__device__ __nv_bfloat16 g_w1t_hi[(size_t)NEXP*HID*DIM];  // [E][H][D] K-major
__device__ __nv_bfloat16 g_w1t_lo[(size_t)NEXP*HID*DIM];
__device__ __nv_bfloat16 g_w2t_hi[(size_t)NEXP*DIM*HID];  // [E][D][H] K-major
__device__ __nv_bfloat16 g_w2t_lo[(size_t)NEXP*DIM*HID];
__device__ __nv_bfloat16 g_Hhi[(size_t)NSLOT*HID];
__device__ __nv_bfloat16 g_Hlo[(size_t)NSLOT*HID];
__device__ float g_Obuf[(size_t)NSLOT*DIM];

// ---------------- PTX helpers ----------------
__device__ __forceinline__ uint32_t smem_u32(const void* p){
    uint32_t a;
    asm("{ .reg .u64 t; cvta.to.shared.u64 t, %1; cvt.u32.u64 %0, t; }" : "=r"(a) : "l"(p));
    return a;
}
#define CP16(dst, src) asm volatile("cp.async.cg.shared.global [%0], [%1], 16;\n" :: "r"(dst), "l"(src))
#define CPCOMMIT()     asm volatile("cp.async.commit_group;\n" ::: "memory")
#define CPWAIT(n)      asm volatile("cp.async.wait_group %0;\n" :: "n"(n) : "memory")
#define SWZ(o) ((o) ^ (((o) >> 3) & 0x70))

__device__ __forceinline__ void ldsm4(uint32_t* r, uint32_t addr){
    asm volatile("ldmatrix.sync.aligned.m8n8.x4.shared.b16 {%0,%1,%2,%3}, [%4];"
        : "=r"(r[0]), "=r"(r[1]), "=r"(r[2]), "=r"(r[3]) : "r"(addr));
}
__device__ __forceinline__ void hmma(float* d, const uint32_t* a, uint32_t b0, uint32_t b1){
    asm volatile("mma.sync.aligned.m16n8k16.row.col.f32.bf16.bf16.f32 "
        "{%0,%1,%2,%3}, {%4,%5,%6,%7}, {%8,%9}, {%0,%1,%2,%3};"
        : "+f"(d[0]), "+f"(d[1]), "+f"(d[2]), "+f"(d[3])
        : "r"(a[0]), "r"(a[1]), "r"(a[2]), "r"(a[3]), "r"(b0), "r"(b1));
}

// ---------------- init ----------------
__global__ void init_kernel(){
    int t = threadIdx.x;
    if (t < NEXP){ g_probsum[t] = 0.f; g_count[t] = 0; }
}

// ---------------- router ----------------
__global__ void router_kernel(const float* __restrict__ x, const float* __restrict__ Wr,
                              const float* __restrict__ br){
    __shared__ float sWr[DIM*NEXP];
    __shared__ float sPs[NEXP];
    __shared__ int   sCnt[NEXP];
    int tid = threadIdx.x;
    for (int i = tid; i < DIM*NEXP; i += 256) sWr[i] = Wr[i];
    if (tid < NEXP){ sPs[tid] = 0.f; sCnt[tid] = 0; }
    __syncthreads();

    int warp = tid >> 5, lane = tid & 31;
    int t = blockIdx.x * 8 + warp;

    float acc[NEXP];
    #pragma unroll
    for (int e = 0; e < NEXP; e++) acc[e] = 0.f;
    const float* xr = x + (size_t)t * DIM;
    for (int d = lane; d < DIM; d += 32){
        float xv = xr[d];
        #pragma unroll
        for (int e = 0; e < NEXP; e++) acc[e] += xv * sWr[d*NEXP + e];
    }
    #pragma unroll
    for (int e = 0; e < NEXP; e++){
        #pragma unroll
        for (int o = 16; o > 0; o >>= 1) acc[e] += __shfl_xor_sync(0xffffffffu, acc[e], o);
    }
    if (lane == 0){
        float l[NEXP];
        float m = -1e30f;
        #pragma unroll
        for (int e = 0; e < NEXP; e++){ l[e] = acc[e] + br[e]; m = fmaxf(m, l[e]); }
        float s = 0.f;
        #pragma unroll
        for (int e = 0; e < NEXP; e++){ l[e] = expf(l[e] - m); s += l[e]; }
        float inv = 1.f / s;
        float p[NEXP];
        #pragma unroll
        for (int e = 0; e < NEXP; e++) p[e] = l[e] * inv;
        int i1 = 0;
        #pragma unroll
        for (int e = 1; e < NEXP; e++) if (p[e] > p[i1]) i1 = e;
        int i2 = (i1 == 0) ? 1 : 0;
        #pragma unroll
        for (int e = 0; e < NEXP; e++) if (e != i1 && p[e] > p[i2]) i2 = e;
        g_eidx[2*t] = i1; g_eidx[2*t+1] = i2;
        g_w[2*t] = p[i1]; g_w[2*t+1] = p[i2];
        #pragma unroll
        for (int e = 0; e < NEXP; e++) atomicAdd(&sPs[e], p[e]);
        atomicAdd(&sCnt[i1], 1); atomicAdd(&sCnt[i2], 1);
    }
    __syncthreads();
    if (tid < NEXP){
        atomicAdd(&g_probsum[tid], sPs[tid]);
        atomicAdd(&g_count[tid], sCnt[tid]);
    }
}

// ---------------- finalize ----------------
__global__ void finalize_kernel(float* __restrict__ loss_out){
    if (threadIdx.x == 0){
        int off = 0;
        for (int e = 0; e < NEXP; e++){
            g_off[e] = off; g_cursor[e] = off; off += g_count[e];
        }
        g_off[NEXP] = off;
        int nt = 0;
        for (int e = 0; e < NEXP; e++){
            for (int r = g_off[e]; r < g_off[e+1]; r += 128){
                g_tile_e[nt] = e;
                g_tile_r0[nt] = r;
                int c = g_off[e+1] - r;
                g_tile_cnt[nt] = c < 128 ? c : 128;
                nt++;
            }
        }
        g_ntiles = nt;
        float lsum = 0.f;
        for (int e = 0; e < NEXP; e++){
            float mp = g_probsum[e] * (1.f/(float)NTOK);
            float d = (1.f/(float)NEXP) - mp;
            lsum += d*d;
        }
        *loss_out = (lsum / (float)NEXP) * 1e-4f;
    }
}

// ---------------- scatter ----------------
__global__ void scatter_kernel(){
    int t = blockIdx.x * 256 + threadIdx.x;
    #pragma unroll
    for (int k = 0; k < 2; k++){
        int e = g_eidx[2*t + k];
        int s = atomicAdd(&g_cursor[e], 1);
        g_tok[s] = t;
        g_slot[2*t + k] = s;
    }
}

// ---------------- convert x -> bf16 hi/lo ----------------
__global__ void convert_x_kernel(const float* __restrict__ x){
    int gid = blockIdx.x * 256 + threadIdx.x;    // NTOK*DIM/4 elems
    float4 v = reinterpret_cast<const float4*>(x)[gid];
    float f[4] = {v.x, v.y, v.z, v.w};
    __nv_bfloat16 h[4], l[4];
    #pragma unroll
    for (int i = 0; i < 4; i++){
        h[i] = __float2bfloat16_rn(f[i]);
        l[i] = __float2bfloat16_rn(f[i] - __bfloat162float(h[i]));
    }
    __nv_bfloat162 h0(h[0], h[1]), h1(h[2], h[3]), l0(l[0], l[1]), l1(l[2], l[3]);
    uint2 hp = make_uint2(*reinterpret_cast<uint32_t*>(&h0), *reinterpret_cast<uint32_t*>(&h1));
    uint2 lp = make_uint2(*reinterpret_cast<uint32_t*>(&l0), *reinterpret_cast<uint32_t*>(&l1));
    reinterpret_cast<uint2*>(g_xhi)[gid] = hp;
    reinterpret_cast<uint2*>(g_xlo)[gid] = lp;
}

// ---------------- transpose + convert weights: W[E][R][C] -> T[E][C][R] hi/lo --
template<int WID>   // 0: W1 (R=DIM,C=HID), 1: W2 (R=HID,C=DIM)
__global__ void convert_wT_kernel(const float* __restrict__ W){
    constexpr int R = (WID == 0) ? DIM : HID;
    constexpr int C = (WID == 0) ? HID : DIM;
    __nv_bfloat16* Thi = (WID == 0) ? g_w1t_hi : g_w2t_hi;
    __nv_bfloat16* Tlo = (WID == 0) ? g_w1t_lo : g_w2t_lo;
    __shared__ float ts[32][33];
    int e = blockIdx.z;
    int cb = blockIdx.x * 32, rb = blockIdx.y * 32;
    int tx = threadIdx.x & 31, ty = threadIdx.x >> 5;
    const float* Wp = W + (size_t)e * R * C;
    #pragma unroll
    for (int j = 0; j < 32; j += 8)
        ts[ty + j][tx] = Wp[(size_t)(rb + ty + j) * C + cb + tx];
    __syncthreads();
    size_t obase = (size_t)e * C * R;
    #pragma unroll
    for (int j = 0; j < 32; j += 8){
        float v = ts[tx][ty + j];
        __nv_bfloat16 h = __float2bfloat16_rn(v);
        __nv_bfloat16 lo = __float2bfloat16_rn(v - __bfloat162float(h));
        size_t o = obase + (size_t)(cb + ty + j) * R + rb + tx;
        Thi[o] = h; Tlo[o] = lo;
    }
}

// ---------------- HMMA grouped GEMM (bf16x3, 3-stage, depth-1, frag dbuf) -----
// MODE 0: H = leaky(gather(x) @ W1[e] + b1[e])  -> g_Hhi/g_Hlo,  K=512,  NCOLS=1024
// MODE 1: O = leaky(H @ W2[e] + b2[e])          -> g_Obuf,       K=1024, NCOLS=512
// Grid: (NCOLS/128, MAXTILES) — n-blocks fastest so sibling CTAs sharing one
// A row-tile run concurrently and A re-reads hit L2 instead of DRAM.
template<int MODE>
__global__ __launch_bounds__(256, 1) void ffn_gemm_mma(const float* __restrict__ bias){
    constexpr int K     = (MODE == 0) ? DIM : HID;
    constexpr int NCOLS = (MODE == 0) ? HID : DIM;
    constexpr int KT    = K / 64;

    int bt = blockIdx.y;
    if (bt >= g_ntiles) return;
    int e   = g_tile_e[bt];
    int r0  = g_tile_r0[bt];
    int cnt = g_tile_cnt[bt];
    int n0  = blockIdx.x * 128;
    int tid = threadIdx.x, wid = tid >> 5, lid = tid & 31;

    const __nv_bfloat16* Ah = (MODE == 0) ? g_xhi : g_Hhi;
    const __nv_bfloat16* Al = (MODE == 0) ? g_xlo : g_Hlo;
    const __nv_bfloat16* Bh = (MODE == 0) ? g_w1t_hi : g_w2t_hi;
    const __nv_bfloat16* Bl = (MODE == 0) ? g_w1t_lo : g_w2t_lo;
    const float* biasp = bias + e * NCOLS;

    extern __shared__ char dsm[];
    uint32_t sbase = smem_u32(dsm);

    // ---- loader mapping: 4 iters x 4 arrays, 16B each ----
    int ga[4], gb[4]; uint32_t dsw[4]; int s8[4];
    #pragma unroll
    for (int i = 0; i < 4; i++){
        int idx = i*256 + tid;
        int row = idx >> 3, sb = idx & 7;
        s8[i]  = sb * 8;
        dsw[i] = SWZ((uint32_t)(row*128 + sb*16));
        int ar = (row < cnt) ? row : (cnt - 1);
        ga[i]  = (MODE == 0) ? g_tok[r0 + ar] : (r0 + ar);
        gb[i]  = e * NCOLS + n0 + row;
    }
    auto load_chunk = [&](int kc, int bb){
        uint32_t base = sbase + (uint32_t)bb * 65536u;
        int koff = kc * 64;
        #pragma unroll
        for (int i = 0; i < 4; i++){
            size_t ao = (size_t)ga[i] * K + koff + s8[i];
            size_t bo = (size_t)gb[i] * K + koff + s8[i];
            CP16(base +         dsw[i], Ah + ao);
            CP16(base + 16384 + dsw[i], Al + ao);
            CP16(base + 32768 + dsw[i], Bh + bo);
            CP16(base + 49152 + dsw[i], Bl + bo);
        }
        CPCOMMIT();
    };

    // ---- per-lane ldmatrix addressing ----
    int wm = wid >> 1;                 // 0..3 -> m base wm*32
    int wn = wid & 1;                  // 0..1 -> n base wn*64
    uint32_t mask = (uint32_t)(lid & 7) << 4;
    uint32_t kx[4];
    #pragma unroll
    for (int ks = 0; ks < 4; ks++) kx[ks] = ((uint32_t)((lid >> 4)*16 + ks*32)) ^ mask;
    uint32_t arow[2], brow[4];
    #pragma unroll
    for (int mt = 0; mt < 2; mt++) arow[mt] = (uint32_t)((wm*32 + mt*16 + (lid & 15)) * 128);
    #pragma unroll
    for (int nt = 0; nt < 4; nt++) brow[nt] = (uint32_t)((wn*64 + nt*16 + (lid & 15)) * 128);

    // fragment double buffers
    uint32_t fah[2][8], fal[2][8], fbh[2][16], fbl[2][16];

    auto load_frags = [&](int pb, uint32_t stage, uint32_t ko){
        #pragma unroll
        for (int mt = 0; mt < 2; mt++){
            ldsm4(&fah[pb][4*mt], stage +          arow[mt] + ko);
            ldsm4(&fal[pb][4*mt], stage + 16384u + arow[mt] + ko);
        }
        #pragma unroll
        for (int nt = 0; nt < 4; nt++){
            ldsm4(&fbh[pb][4*nt], stage + 32768u + brow[nt] + ko);
            ldsm4(&fbl[pb][4*nt], stage + 49152u + brow[nt] + ko);
        }
    };

    float acc[2][8][4];
    #pragma unroll
    for (int mt = 0; mt < 2; mt++)
        #pragma unroll
        for (int j = 0; j < 8; j++)
            #pragma unroll
            for (int q = 0; q < 4; q++) acc[mt][j][q] = 0.f;

    auto mma_all = [&](int pb){
        #pragma unroll
        for (int mt = 0; mt < 2; mt++){
            #pragma unroll
            for (int j = 0; j < 8; j++){
                int nt = j >> 1, s = j & 1;
                hmma(acc[mt][j], &fah[pb][4*mt], fbh[pb][4*nt + s], fbh[pb][4*nt + s + 2]);
                hmma(acc[mt][j], &fah[pb][4*mt], fbl[pb][4*nt + s], fbl[pb][4*nt + s + 2]);
                hmma(acc[mt][j], &fal[pb][4*mt], fbh[pb][4*nt + s], fbh[pb][4*nt + s + 2]);
            }
        }
    };

    // prologue: stage 0 in flight, wait, then depth-1 prefetch of stage 1
    load_chunk(0, 0);
    CPWAIT(0);
    __syncthreads();
    load_chunk(1, 1);
    load_frags(0, sbase, kx[0]);

    for (int kt = 0; kt < KT; kt++){
        uint32_t stage = sbase + (uint32_t)(kt % 3) * 65536u;
        #pragma unroll
        for (int ks = 0; ks < 4; ks++){
            int pb = ks & 1;
            if (ks < 3) load_frags(pb ^ 1, stage, kx[ks + 1]);
            mma_all(pb);
        }
        if (kt + 1 < KT){
            CPWAIT(0);
            __syncthreads();
            if (kt + 2 < KT) load_chunk(kt + 2, (kt + 2) % 3);
            load_frags(0, sbase + (uint32_t)((kt + 1) % 3) * 65536u, kx[0]);
        }
    }

    // ---- epilogue: bias + LeakyReLU, write C ----
    int mq = lid >> 2;          // 0..7
    int nq = (lid & 3) * 2;     // 0,2,4,6
    #pragma unroll
    for (int mt = 0; mt < 2; mt++){
        #pragma unroll
        for (int half = 0; half < 2; half++){
            int ml = wm*32 + mt*16 + half*8 + mq;
            if (ml >= cnt) continue;
            size_t orow = (size_t)(r0 + ml);
            #pragma unroll
            for (int j = 0; j < 8; j++){
                int ncol = n0 + wn*64 + j*8 + nq;
                float v0 = acc[mt][j][2*half]   + biasp[ncol];
                float v1 = acc[mt][j][2*half+1] + biasp[ncol+1];
                v0 = (v0 > 0.f) ? v0 : 0.01f*v0;
                v1 = (v1 > 0.f) ? v1 : 0.01f*v1;
                if (MODE == 0){
                    __nv_bfloat16 h0 = __float2bfloat16_rn(v0);
                    __nv_bfloat16 h1 = __float2bfloat16_rn(v1);
                    __nv_bfloat16 l0 = __float2bfloat16_rn(v0 - __bfloat162float(h0));
                    __nv_bfloat16 l1 = __float2bfloat16_rn(v1 - __bfloat162float(h1));
                    __nv_bfloat162 hh(h0, h1), ll(l0, l1);
                    *reinterpret_cast<uint32_t*>(&g_Hhi[orow*HID + ncol]) = *reinterpret_cast<uint32_t*>(&hh);
                    *reinterpret_cast<uint32_t*>(&g_Hlo[orow*HID + ncol]) = *reinterpret_cast<uint32_t*>(&ll);
                } else {
                    *reinterpret_cast<float2*>(&g_Obuf[orow*DIM + ncol]) = make_float2(v0, v1);
                }
            }
        }
    }
}

// ---------------- combine ----------------
__global__ void combine_kernel(float* __restrict__ out){
    int gid = blockIdx.x * 256 + threadIdx.x;
    int t = gid >> 7;
    int c = gid & 127;
    int s0 = g_slot[2*t], s1 = g_slot[2*t + 1];
    float w0 = g_w[2*t],  w1 = g_w[2*t + 1];
    const float4* O = reinterpret_cast<const float4*>(g_Obuf);
    float4 a = O[(size_t)s0 * 128 + c];
    float4 b = O[(size_t)s1 * 128 + c];
    float4 r;
    r.x = w0*a.x + w1*b.x;
    r.y = w0*a.y + w1*b.y;
    r.z = w0*a.z + w1*b.z;
    r.w = w0*a.w + w1*b.w;
    reinterpret_cast<float4*>(out)[gid] = r;
}

// ---------------- launch ----------------
extern "C" void kernel_launch(void* const* d_in, const int* in_sizes, int n_in,
                              void* d_out, int out_size){
    const float* x  = (const float*)d_in[0];
    const float* Wr = (const float*)d_in[1];
    const float* br = (const float*)d_in[2];
    const float* W1 = (const float*)d_in[3];
    const float* b1 = (const float*)d_in[4];
    const float* W2 = (const float*)d_in[5];
    const float* b2 = (const float*)d_in[6];
    float* out = (float*)d_out;

    const int SMEM_DYN = 3*65536;
    cudaFuncSetAttribute(ffn_gemm_mma<0>, cudaFuncAttributeMaxDynamicSharedMemorySize, SMEM_DYN);
    cudaFuncSetAttribute(ffn_gemm_mma<1>, cudaFuncAttributeMaxDynamicSharedMemorySize, SMEM_DYN);

    init_kernel<<<1, 32>>>();
    router_kernel<<<NTOK/8, 256>>>(x, Wr, br);
    finalize_kernel<<<1, 32>>>(out + (out_size - 1));
    scatter_kernel<<<NTOK/256, 256>>>();
    convert_x_kernel<<<(NTOK*DIM/4)/256, 256>>>(x);
    convert_wT_kernel<0><<<dim3(HID/32, DIM/32, NEXP), 256>>>(W1);
    convert_wT_kernel<1><<<dim3(DIM/32, HID/32, NEXP), 256>>>(W2);
    ffn_gemm_mma<0><<<dim3(HID/128, MAXTILES), 256, SMEM_DYN>>>(b1);
    ffn_gemm_mma<1><<<dim3(DIM/128, MAXTILES), 256, SMEM_DYN>>>(b2);
    combine_kernel<<<(NTOK*DIM/4)/256, 256>>>(out);
}

// round 6
// speedup vs baseline: 2.5337x; 2.5337x over previous
#include <cuda_runtime.h>
#include <cuda_fp16.h>
#include <cstdint>

#define NTOK 16384
#define DIM  512
#define NEXP 8
#define HID  1024
#define NSLOT (NTOK*2)
#define MAXTILES (NSLOT/128 + NEXP)   // 264

// ---------------- device-global scratch (no allocs allowed) ----------------
__device__ float g_probsum[NEXP];
__device__ int   g_count[NEXP];
__device__ int   g_cursor[NEXP];
__device__ int   g_off[NEXP+1];
__device__ int   g_tile_e[MAXTILES];
__device__ int   g_tile_r0[MAXTILES];
__device__ int   g_tile_cnt[MAXTILES];
__device__ int   g_ntiles;
__device__ int   g_tok[NSLOT];
__device__ int   g_eidx[NTOK*2];
__device__ int   g_slot[NTOK*2];
__device__ float g_w[NTOK*2];

__device__ __half g_xh[(size_t)NTOK*DIM];
__device__ __half g_w1t[(size_t)NEXP*HID*DIM];  // [E][H][D] K-major
__device__ __half g_w2t[(size_t)NEXP*DIM*HID];  // [E][D][H] K-major
__device__ __half g_Hh[(size_t)NSLOT*HID];
__device__ float  g_Obuf[(size_t)NSLOT*DIM];

// ---------------- PTX helpers ----------------
__device__ __forceinline__ uint32_t smem_u32(const void* p){
    uint32_t a;
    asm("{ .reg .u64 t; cvta.to.shared.u64 t, %1; cvt.u32.u64 %0, t; }" : "=r"(a) : "l"(p));
    return a;
}
#define CP16(dst, src) asm volatile("cp.async.cg.shared.global [%0], [%1], 16;\n" :: "r"(dst), "l"(src))
#define CPCOMMIT()     asm volatile("cp.async.commit_group;\n" ::: "memory")
#define CPWAIT(n)      asm volatile("cp.async.wait_group %0;\n" :: "n"(n) : "memory")
#define SWZ(o) ((o) ^ (((o) >> 3) & 0x70))

__device__ __forceinline__ void ldsm4(uint32_t* r, uint32_t addr){
    asm volatile("ldmatrix.sync.aligned.m8n8.x4.shared.b16 {%0,%1,%2,%3}, [%4];"
        : "=r"(r[0]), "=r"(r[1]), "=r"(r[2]), "=r"(r[3]) : "r"(addr));
}
__device__ __forceinline__ void hmma(float* d, const uint32_t* a, uint32_t b0, uint32_t b1){
    asm volatile("mma.sync.aligned.m16n8k16.row.col.f32.f16.f16.f32 "
        "{%0,%1,%2,%3}, {%4,%5,%6,%7}, {%8,%9}, {%0,%1,%2,%3};"
        : "+f"(d[0]), "+f"(d[1]), "+f"(d[2]), "+f"(d[3])
        : "r"(a[0]), "r"(a[1]), "r"(a[2]), "r"(a[3]), "r"(b0), "r"(b1));
}

// ---------------- init ----------------
__global__ void init_kernel(){
    int t = threadIdx.x;
    if (t < NEXP){ g_probsum[t] = 0.f; g_count[t] = 0; }
}

// ---------------- router ----------------
__global__ void router_kernel(const float* __restrict__ x, const float* __restrict__ Wr,
                              const float* __restrict__ br){
    __shared__ float sWr[DIM*NEXP];
    __shared__ float sPs[NEXP];
    __shared__ int   sCnt[NEXP];
    int tid = threadIdx.x;
    for (int i = tid; i < DIM*NEXP; i += 256) sWr[i] = Wr[i];
    if (tid < NEXP){ sPs[tid] = 0.f; sCnt[tid] = 0; }
    __syncthreads();

    int warp = tid >> 5, lane = tid & 31;
    int t = blockIdx.x * 8 + warp;

    float acc[NEXP];
    #pragma unroll
    for (int e = 0; e < NEXP; e++) acc[e] = 0.f;
    const float* xr = x + (size_t)t * DIM;
    for (int d = lane; d < DIM; d += 32){
        float xv = xr[d];
        #pragma unroll
        for (int e = 0; e < NEXP; e++) acc[e] += xv * sWr[d*NEXP + e];
    }
    #pragma unroll
    for (int e = 0; e < NEXP; e++){
        #pragma unroll
        for (int o = 16; o > 0; o >>= 1) acc[e] += __shfl_xor_sync(0xffffffffu, acc[e], o);
    }
    if (lane == 0){
        float l[NEXP];
        float m = -1e30f;
        #pragma unroll
        for (int e = 0; e < NEXP; e++){ l[e] = acc[e] + br[e]; m = fmaxf(m, l[e]); }
        float s = 0.f;
        #pragma unroll
        for (int e = 0; e < NEXP; e++){ l[e] = expf(l[e] - m); s += l[e]; }
        float inv = 1.f / s;
        float p[NEXP];
        #pragma unroll
        for (int e = 0; e < NEXP; e++) p[e] = l[e] * inv;
        int i1 = 0;
        #pragma unroll
        for (int e = 1; e < NEXP; e++) if (p[e] > p[i1]) i1 = e;
        int i2 = (i1 == 0) ? 1 : 0;
        #pragma unroll
        for (int e = 0; e < NEXP; e++) if (e != i1 && p[e] > p[i2]) i2 = e;
        g_eidx[2*t] = i1; g_eidx[2*t+1] = i2;
        g_w[2*t] = p[i1]; g_w[2*t+1] = p[i2];
        #pragma unroll
        for (int e = 0; e < NEXP; e++) atomicAdd(&sPs[e], p[e]);
        atomicAdd(&sCnt[i1], 1); atomicAdd(&sCnt[i2], 1);
    }
    __syncthreads();
    if (tid < NEXP){
        atomicAdd(&g_probsum[tid], sPs[tid]);
        atomicAdd(&g_count[tid], sCnt[tid]);
    }
}

// ---------------- finalize ----------------
__global__ void finalize_kernel(float* __restrict__ loss_out){
    if (threadIdx.x == 0){
        int off = 0;
        for (int e = 0; e < NEXP; e++){
            g_off[e] = off; g_cursor[e] = off; off += g_count[e];
        }
        g_off[NEXP] = off;
        int nt = 0;
        for (int e = 0; e < NEXP; e++){
            for (int r = g_off[e]; r < g_off[e+1]; r += 128){
                g_tile_e[nt] = e;
                g_tile_r0[nt] = r;
                int c = g_off[e+1] - r;
                g_tile_cnt[nt] = c < 128 ? c : 128;
                nt++;
            }
        }
        g_ntiles = nt;
        float lsum = 0.f;
        for (int e = 0; e < NEXP; e++){
            float mp = g_probsum[e] * (1.f/(float)NTOK);
            float d = (1.f/(float)NEXP) - mp;
            lsum += d*d;
        }
        *loss_out = (lsum / (float)NEXP) * 1e-4f;
    }
}

// ---------------- scatter ----------------
__global__ void scatter_kernel(){
    int t = blockIdx.x * 256 + threadIdx.x;
    #pragma unroll
    for (int k = 0; k < 2; k++){
        int e = g_eidx[2*t + k];
        int s = atomicAdd(&g_cursor[e], 1);
        g_tok[s] = t;
        g_slot[2*t + k] = s;
    }
}

// ---------------- convert x -> fp16 ----------------
__global__ void convert_x_kernel(const float* __restrict__ x){
    int gid = blockIdx.x * 256 + threadIdx.x;    // NTOK*DIM/4 elems
    float4 v = reinterpret_cast<const float4*>(x)[gid];
    __half2 h0 = __floats2half2_rn(v.x, v.y);
    __half2 h1 = __floats2half2_rn(v.z, v.w);
    uint2 hp = make_uint2(*reinterpret_cast<uint32_t*>(&h0), *reinterpret_cast<uint32_t*>(&h1));
    reinterpret_cast<uint2*>(g_xh)[gid] = hp;
}

// ---------------- transpose + convert weights: W[E][R][C] -> T[E][C][R] fp16 --
template<int WID>   // 0: W1 (R=DIM,C=HID), 1: W2 (R=HID,C=DIM)
__global__ void convert_wT_kernel(const float* __restrict__ W){
    constexpr int R = (WID == 0) ? DIM : HID;
    constexpr int C = (WID == 0) ? HID : DIM;
    __half* T = (WID == 0) ? g_w1t : g_w2t;
    __shared__ float ts[32][33];
    int e = blockIdx.z;
    int cb = blockIdx.x * 32, rb = blockIdx.y * 32;
    int tx = threadIdx.x & 31, ty = threadIdx.x >> 5;
    const float* Wp = W + (size_t)e * R * C;
    #pragma unroll
    for (int j = 0; j < 32; j += 8)
        ts[ty + j][tx] = Wp[(size_t)(rb + ty + j) * C + cb + tx];
    __syncthreads();
    size_t obase = (size_t)e * C * R;
    #pragma unroll
    for (int j = 0; j < 32; j += 8){
        float v = ts[tx][ty + j];
        T[obase + (size_t)(cb + ty + j) * R + rb + tx] = __float2half_rn(v);
    }
}

// ---------------- HMMA grouped GEMM (fp16 single-pass, 3-stage cp.async) -----
// MODE 0: H = leaky(gather(x) @ W1[e] + b1[e])  -> g_Hh,   K=512,  NCOLS=1024
// MODE 1: O = leaky(H @ W2[e] + b2[e])          -> g_Obuf, K=1024, NCOLS=512
// Stage = 32 KB: [A 16K][B 16K]; rows of 128B (64 halfs), SWZ swizzle shared by
// cp.async stores and ldmatrix. Grid: (NCOLS/128, tiles) — n-blocks fastest so
// sibling CTAs sharing one A row-tile run concurrently (A re-reads hit L2).
template<int MODE>
__global__ __launch_bounds__(256, 2) void ffn_gemm_mma(const float* __restrict__ bias){
    constexpr int K     = (MODE == 0) ? DIM : HID;
    constexpr int NCOLS = (MODE == 0) ? HID : DIM;
    constexpr int KT    = K / 64;
    constexpr uint32_t STAGE = 32768u;

    int bt = blockIdx.y;
    if (bt >= g_ntiles) return;
    int e   = g_tile_e[bt];
    int r0  = g_tile_r0[bt];
    int cnt = g_tile_cnt[bt];
    int n0  = blockIdx.x * 128;
    int tid = threadIdx.x, wid = tid >> 5, lid = tid & 31;

    const __half* A = (MODE == 0) ? g_xh : g_Hh;
    const __half* B = (MODE == 0) ? g_w1t : g_w2t;
    const float* biasp = bias + e * NCOLS;

    extern __shared__ char dsm[];
    uint32_t sbase = smem_u32(dsm);

    // ---- loader mapping: 4 iters x 2 arrays, 16B each ----
    int ga[4], gb[4]; uint32_t dsw[4]; int s8[4];
    #pragma unroll
    for (int i = 0; i < 4; i++){
        int idx = i*256 + tid;
        int row = idx >> 3, sb = idx & 7;
        s8[i]  = sb * 8;
        dsw[i] = SWZ((uint32_t)(row*128 + sb*16));
        int ar = (row < cnt) ? row : (cnt - 1);
        ga[i]  = (MODE == 0) ? g_tok[r0 + ar] : (r0 + ar);
        gb[i]  = e * NCOLS + n0 + row;
    }
    auto load_chunk = [&](int kc, int bb){
        uint32_t base = sbase + (uint32_t)bb * STAGE;
        int koff = kc * 64;
        #pragma unroll
        for (int i = 0; i < 4; i++){
            size_t ao = (size_t)ga[i] * K + koff + s8[i];
            size_t bo = (size_t)gb[i] * K + koff + s8[i];
            CP16(base +         dsw[i], A + ao);
            CP16(base + 16384 + dsw[i], B + bo);
        }
        CPCOMMIT();
    };

    // ---- per-lane ldmatrix addressing ----
    int wm = wid >> 1;                 // 0..3 -> m base wm*32
    int wn = wid & 1;                  // 0..1 -> n base wn*64
    uint32_t mask = (uint32_t)(lid & 7) << 4;
    uint32_t kx[4];
    #pragma unroll
    for (int ks = 0; ks < 4; ks++) kx[ks] = ((uint32_t)((lid >> 4)*16 + ks*32)) ^ mask;
    uint32_t arow[2], brow[4];
    #pragma unroll
    for (int mt = 0; mt < 2; mt++) arow[mt] = (uint32_t)((wm*32 + mt*16 + (lid & 15)) * 128);
    #pragma unroll
    for (int nt = 0; nt < 4; nt++) brow[nt] = (uint32_t)((wn*64 + nt*16 + (lid & 15)) * 128);

    float acc[2][8][4];
    #pragma unroll
    for (int mt = 0; mt < 2; mt++)
        #pragma unroll
        for (int j = 0; j < 8; j++)
            #pragma unroll
            for (int q = 0; q < 4; q++) acc[mt][j][q] = 0.f;

    load_chunk(0, 0);
    load_chunk(1, 1);

    for (int kt = 0; kt < KT; kt++){
        int b = kt % 3;
        if (kt < KT - 1) { CPWAIT(1); } else { CPWAIT(0); }
        __syncthreads();
        if (kt + 2 < KT) load_chunk(kt + 2, (kt + 2) % 3);

        uint32_t bA = sbase + (uint32_t)b * STAGE;
        uint32_t bB = bA + 16384u;

        #pragma unroll
        for (int ks = 0; ks < 4; ks++){
            uint32_t ko = kx[ks];
            uint32_t fa[2][4], fb[4][4];
            #pragma unroll
            for (int mt = 0; mt < 2; mt++) ldsm4(fa[mt], bA + arow[mt] + ko);
            #pragma unroll
            for (int nt = 0; nt < 4; nt++) ldsm4(fb[nt], bB + brow[nt] + ko);
            #pragma unroll
            for (int mt = 0; mt < 2; mt++){
                #pragma unroll
                for (int j = 0; j < 8; j++){
                    int nt = j >> 1, s = j & 1;
                    hmma(acc[mt][j], fa[mt], fb[nt][s], fb[nt][s+2]);
                }
            }
        }
        __syncthreads();
    }

    // ---- epilogue: bias + LeakyReLU, write C ----
    int mq = lid >> 2;          // 0..7
    int nq = (lid & 3) * 2;     // 0,2,4,6
    #pragma unroll
    for (int mt = 0; mt < 2; mt++){
        #pragma unroll
        for (int half = 0; half < 2; half++){
            int ml = wm*32 + mt*16 + half*8 + mq;
            if (ml >= cnt) continue;
            size_t orow = (size_t)(r0 + ml);
            #pragma unroll
            for (int j = 0; j < 8; j++){
                int ncol = n0 + wn*64 + j*8 + nq;
                float v0 = acc[mt][j][2*half]   + biasp[ncol];
                float v1 = acc[mt][j][2*half+1] + biasp[ncol+1];
                v0 = (v0 > 0.f) ? v0 : 0.01f*v0;
                v1 = (v1 > 0.f) ? v1 : 0.01f*v1;
                if (MODE == 0){
                    __half2 hh = __floats2half2_rn(v0, v1);
                    *reinterpret_cast<uint32_t*>(&g_Hh[orow*HID + ncol]) = *reinterpret_cast<uint32_t*>(&hh);
                } else {
                    *reinterpret_cast<float2*>(&g_Obuf[orow*DIM + ncol]) = make_float2(v0, v1);
                }
            }
        }
    }
}

// ---------------- combine ----------------
__global__ void combine_kernel(float* __restrict__ out){
    int gid = blockIdx.x * 256 + threadIdx.x;
    int t = gid >> 7;
    int c = gid & 127;
    int s0 = g_slot[2*t], s1 = g_slot[2*t + 1];
    float w0 = g_w[2*t],  w1 = g_w[2*t + 1];
    const float4* O = reinterpret_cast<const float4*>(g_Obuf);
    float4 a = O[(size_t)s0 * 128 + c];
    float4 b = O[(size_t)s1 * 128 + c];
    float4 r;
    r.x = w0*a.x + w1*b.x;
    r.y = w0*a.y + w1*b.y;
    r.z = w0*a.z + w1*b.z;
    r.w = w0*a.w + w1*b.w;
    reinterpret_cast<float4*>(out)[gid] = r;
}

// ---------------- launch ----------------
extern "C" void kernel_launch(void* const* d_in, const int* in_sizes, int n_in,
                              void* d_out, int out_size){
    const float* x  = (const float*)d_in[0];
    const float* Wr = (const float*)d_in[1];
    const float* br = (const float*)d_in[2];
    const float* W1 = (const float*)d_in[3];
    const float* b1 = (const float*)d_in[4];
    const float* W2 = (const float*)d_in[5];
    const float* b2 = (const float*)d_in[6];
    float* out = (float*)d_out;

    const int SMEM_DYN = 3*32768;
    cudaFuncSetAttribute(ffn_gemm_mma<0>, cudaFuncAttributeMaxDynamicSharedMemorySize, SMEM_DYN);
    cudaFuncSetAttribute(ffn_gemm_mma<1>, cudaFuncAttributeMaxDynamicSharedMemorySize, SMEM_DYN);

    init_kernel<<<1, 32>>>();
    router_kernel<<<NTOK/8, 256>>>(x, Wr, br);
    finalize_kernel<<<1, 32>>>(out + (out_size - 1));
    scatter_kernel<<<NTOK/256, 256>>>();
    convert_x_kernel<<<(NTOK*DIM/4)/256, 256>>>(x);
    convert_wT_kernel<0><<<dim3(HID/32, DIM/32, NEXP), 256>>>(W1);
    convert_wT_kernel<1><<<dim3(DIM/32, HID/32, NEXP), 256>>>(W2);
    ffn_gemm_mma<0><<<dim3(HID/128, MAXTILES), 256, SMEM_DYN>>>(b1);
    ffn_gemm_mma<1><<<dim3(DIM/128, MAXTILES), 256, SMEM_DYN>>>(b2);
    combine_kernel<<<(NTOK*DIM/4)/256, 256>>>(out);
}

// round 8
// speedup vs baseline: 2.6065x; 1.0287x over previous
#include <cuda_runtime.h>
#include <cuda_fp16.h>
#include <cstdint>

#define NTOK 16384
#define DIM  512
#define NEXP 8
#define HID  1024
#define NSLOT (NTOK*2)
#define MAXTILES (NSLOT/128 + NEXP)   // 264

// ---------------- device-global scratch (no allocs allowed) ----------------
__device__ float g_probsum[NEXP];
__device__ int   g_count[NEXP];
__device__ int   g_cursor[NEXP];
__device__ int   g_tile_e[MAXTILES];
__device__ int   g_tile_r0[MAXTILES];
__device__ int   g_tile_cnt[MAXTILES];
__device__ int   g_ntiles;
__device__ int   g_tok[NSLOT];          // slot -> token
__device__ float g_wslot[NSLOT];        // slot -> router weight
__device__ int   g_eidx[NTOK*2];        // token -> (e0,e1)
__device__ float g_w[NTOK*2];           // token -> (w0,w1)

__device__ __half g_xh[(size_t)NTOK*DIM];
__device__ __half g_w1t[(size_t)NEXP*HID*DIM];  // [E][H][D] K-major
__device__ __half g_w2t[(size_t)NEXP*DIM*HID];  // [E][D][H] K-major
__device__ __half g_Hh[(size_t)NSLOT*HID];

// ---------------- PTX helpers ----------------
__device__ __forceinline__ uint32_t smem_u32(const void* p){
    uint32_t a;
    asm("{ .reg .u64 t; cvta.to.shared.u64 t, %1; cvt.u32.u64 %0, t; }" : "=r"(a) : "l"(p));
    return a;
}
#define CP16(dst, src) asm volatile("cp.async.cg.shared.global [%0], [%1], 16;\n" :: "r"(dst), "l"(src))
#define CPCOMMIT()     asm volatile("cp.async.commit_group;\n" ::: "memory")
#define CPWAIT(n)      asm volatile("cp.async.wait_group %0;\n" :: "n"(n) : "memory")
#define SWZ(o) ((o) ^ (((o) >> 3) & 0x70))

__device__ __forceinline__ void ldsm4(uint32_t* r, uint32_t addr){
    asm volatile("ldmatrix.sync.aligned.m8n8.x4.shared.b16 {%0,%1,%2,%3}, [%4];"
        : "=r"(r[0]), "=r"(r[1]), "=r"(r[2]), "=r"(r[3]) : "r"(addr));
}
__device__ __forceinline__ void hmma(float* d, const uint32_t* a, uint32_t b0, uint32_t b1){
    asm volatile("mma.sync.aligned.m16n8k16.row.col.f32.f16.f16.f32 "
        "{%0,%1,%2,%3}, {%4,%5,%6,%7}, {%8,%9}, {%0,%1,%2,%3};"
        : "+f"(d[0]), "+f"(d[1]), "+f"(d[2]), "+f"(d[3])
        : "r"(a[0]), "r"(a[1]), "r"(a[2]), "r"(a[3]), "r"(b0), "r"(b1));
}

// ---------------- zero output + init counters ----------------
__global__ void zero_out_kernel(float* __restrict__ out){
    int gid = blockIdx.x * 256 + threadIdx.x;    // NTOK*DIM/4 float4s
    reinterpret_cast<float4*>(out)[gid] = make_float4(0.f, 0.f, 0.f, 0.f);
    if (blockIdx.x == 0 && threadIdx.x < NEXP){
        g_probsum[threadIdx.x] = 0.f;
        g_count[threadIdx.x] = 0;
    }
}

// ---------------- router (+ fused x->fp16 convert) ----------------
__global__ void router_kernel(const float* __restrict__ x, const float* __restrict__ Wr,
                              const float* __restrict__ br){
    __shared__ float sWr[DIM*NEXP];
    __shared__ float sPs[NEXP];
    __shared__ int   sCnt[NEXP];
    int tid = threadIdx.x;
    for (int i = tid; i < DIM*NEXP; i += 256) sWr[i] = Wr[i];
    if (tid < NEXP){ sPs[tid] = 0.f; sCnt[tid] = 0; }
    __syncthreads();

    int warp = tid >> 5, lane = tid & 31;
    int t = blockIdx.x * 8 + warp;

    float acc[NEXP];
    #pragma unroll
    for (int e = 0; e < NEXP; e++) acc[e] = 0.f;
    const float* xr = x + (size_t)t * DIM;
    __half* xh = g_xh + (size_t)t * DIM;
    for (int d = lane; d < DIM; d += 32){
        float xv = xr[d];
        xh[d] = __float2half_rn(xv);
        #pragma unroll
        for (int e = 0; e < NEXP; e++) acc[e] += xv * sWr[d*NEXP + e];
    }
    #pragma unroll
    for (int e = 0; e < NEXP; e++){
        #pragma unroll
        for (int o = 16; o > 0; o >>= 1) acc[e] += __shfl_xor_sync(0xffffffffu, acc[e], o);
    }
    if (lane == 0){
        float l[NEXP];
        float m = -1e30f;
        #pragma unroll
        for (int e = 0; e < NEXP; e++){ l[e] = acc[e] + br[e]; m = fmaxf(m, l[e]); }
        float s = 0.f;
        #pragma unroll
        for (int e = 0; e < NEXP; e++){ l[e] = expf(l[e] - m); s += l[e]; }
        float inv = 1.f / s;
        float p[NEXP];
        #pragma unroll
        for (int e = 0; e < NEXP; e++) p[e] = l[e] * inv;
        int i1 = 0;
        #pragma unroll
        for (int e = 1; e < NEXP; e++) if (p[e] > p[i1]) i1 = e;
        int i2 = (i1 == 0) ? 1 : 0;
        #pragma unroll
        for (int e = 0; e < NEXP; e++) if (e != i1 && p[e] > p[i2]) i2 = e;
        g_eidx[2*t] = i1; g_eidx[2*t+1] = i2;
        g_w[2*t] = p[i1]; g_w[2*t+1] = p[i2];
        #pragma unroll
        for (int e = 0; e < NEXP; e++) atomicAdd(&sPs[e], p[e]);
        atomicAdd(&sCnt[i1], 1); atomicAdd(&sCnt[i2], 1);
    }
    __syncthreads();
    if (tid < NEXP){
        atomicAdd(&g_probsum[tid], sPs[tid]);
        atomicAdd(&g_count[tid], sCnt[tid]);
    }
}

// ---------------- finalize: offsets, tile table, gating loss (1 warp) --------
__global__ void finalize_kernel(float* __restrict__ loss_out){
    int lane = threadIdx.x;                 // 32 threads
    int cnt = (lane < NEXP) ? g_count[lane] : 0;
    // inclusive prefix over lanes
    int inc = cnt;
    #pragma unroll
    for (int o = 1; o < 32; o <<= 1){
        int v = __shfl_up_sync(0xffffffffu, inc, o);
        if (lane >= o) inc += v;
    }
    int off = inc - cnt;                    // exclusive
    if (lane < NEXP) g_cursor[lane] = off;

    int nt = (cnt + 127) >> 7;
    int ninc = nt;
    #pragma unroll
    for (int o = 1; o < 32; o <<= 1){
        int v = __shfl_up_sync(0xffffffffu, ninc, o);
        if (lane >= o) ninc += v;
    }
    int tb = ninc - nt;
    if (lane == NEXP - 1) g_ntiles = tb + nt;
    if (lane < NEXP){
        for (int i = 0; i < nt; i++){
            int r = off + i*128;
            g_tile_e[tb + i] = lane;
            g_tile_r0[tb + i] = r;
            int c = cnt - i*128;
            g_tile_cnt[tb + i] = c < 128 ? c : 128;
        }
    }
    // gating loss
    float d = 0.f;
    if (lane < NEXP){
        float mp = g_probsum[lane] * (1.f/(float)NTOK);
        float dd = (1.f/(float)NEXP) - mp;
        d = dd*dd;
    }
    #pragma unroll
    for (int o = 16; o > 0; o >>= 1) d += __shfl_xor_sync(0xffffffffu, d, o);
    if (lane == 0) *loss_out = (d / (float)NEXP) * 1e-4f;
}

// ---------------- scatter ----------------
__global__ void scatter_kernel(){
    int t = blockIdx.x * 256 + threadIdx.x;
    #pragma unroll
    for (int k = 0; k < 2; k++){
        int e = g_eidx[2*t + k];
        int s = atomicAdd(&g_cursor[e], 1);
        g_tok[s] = t;
        g_wslot[s] = g_w[2*t + k];
    }
}

// ---------------- transpose + convert weights: W[E][R][C] -> T[E][C][R] fp16 --
template<int WID>   // 0: W1 (R=DIM,C=HID), 1: W2 (R=HID,C=DIM)
__global__ void convert_wT_kernel(const float* __restrict__ W){
    constexpr int R = (WID == 0) ? DIM : HID;
    constexpr int C = (WID == 0) ? HID : DIM;
    __half* T = (WID == 0) ? g_w1t : g_w2t;
    __shared__ float ts[32][33];
    int e = blockIdx.z;
    int cb = blockIdx.x * 32, rb = blockIdx.y * 32;
    int tx = threadIdx.x & 31, ty = threadIdx.x >> 5;
    const float* Wp = W + (size_t)e * R * C;
    #pragma unroll
    for (int j = 0; j < 32; j += 8)
        ts[ty + j][tx] = Wp[(size_t)(rb + ty + j) * C + cb + tx];
    __syncthreads();
    size_t obase = (size_t)e * C * R;
    #pragma unroll
    for (int j = 0; j < 32; j += 8){
        float v = ts[tx][ty + j];
        T[obase + (size_t)(cb + ty + j) * R + rb + tx] = __float2half_rn(v);
    }
}

// ---------------- HMMA grouped GEMM (fp16 single-pass, 3-stage cp.async) -----
// MODE 0: H = leaky(gather(x) @ W1[e] + b1[e])  -> g_Hh,   K=512,  NCOLS=1024
// MODE 1: out[token] += w_slot * leaky(H @ W2[e] + b2[e])  (fused combine)
template<int MODE>
__global__ __launch_bounds__(256, 2) void ffn_gemm_mma(const float* __restrict__ bias,
                                                       float* __restrict__ out){
    constexpr int K     = (MODE == 0) ? DIM : HID;
    constexpr int NCOLS = (MODE == 0) ? HID : DIM;
    constexpr int KT    = K / 64;
    constexpr uint32_t STAGE = 32768u;

    int bt = blockIdx.y;
    if (bt >= g_ntiles) return;
    int e   = g_tile_e[bt];
    int r0  = g_tile_r0[bt];
    int cnt = g_tile_cnt[bt];
    int n0  = blockIdx.x * 128;
    int tid = threadIdx.x, wid = tid >> 5, lid = tid & 31;

    const __half* A = (MODE == 0) ? g_xh : g_Hh;
    const __half* B = (MODE == 0) ? g_w1t : g_w2t;
    const float* biasp = bias + e * NCOLS;

    extern __shared__ char dsm[];
    uint32_t sbase = smem_u32(dsm);

    // ---- loader mapping: 4 iters x 2 arrays, 16B each ----
    int ga[4], gb[4]; uint32_t dsw[4]; int s8[4];
    #pragma unroll
    for (int i = 0; i < 4; i++){
        int idx = i*256 + tid;
        int row = idx >> 3, sb = idx & 7;
        s8[i]  = sb * 8;
        dsw[i] = SWZ((uint32_t)(row*128 + sb*16));
        int ar = (row < cnt) ? row : (cnt - 1);
        ga[i]  = (MODE == 0) ? g_tok[r0 + ar] : (r0 + ar);
        gb[i]  = e * NCOLS + n0 + row;
    }
    auto load_chunk = [&](int kc, int bb){
        uint32_t base = sbase + (uint32_t)bb * STAGE;
        int koff = kc * 64;
        #pragma unroll
        for (int i = 0; i < 4; i++){
            size_t ao = (size_t)ga[i] * K + koff + s8[i];
            size_t bo = (size_t)gb[i] * K + koff + s8[i];
            CP16(base +         dsw[i], A + ao);
            CP16(base + 16384 + dsw[i], B + bo);
        }
        CPCOMMIT();
    };

    // ---- per-lane ldmatrix addressing ----
    int wm = wid >> 1;                 // 0..3 -> m base wm*32
    int wn = wid & 1;                  // 0..1 -> n base wn*64
    uint32_t mask = (uint32_t)(lid & 7) << 4;
    uint32_t kx[4];
    #pragma unroll
    for (int ks = 0; ks < 4; ks++) kx[ks] = ((uint32_t)((lid >> 4)*16 + ks*32)) ^ mask;
    uint32_t arow[2], brow[4];
    #pragma unroll
    for (int mt = 0; mt < 2; mt++) arow[mt] = (uint32_t)((wm*32 + mt*16 + (lid & 15)) * 128);
    #pragma unroll
    for (int nt = 0; nt < 4; nt++) brow[nt] = (uint32_t)((wn*64 + nt*16 + (lid & 15)) * 128);

    float acc[2][8][4];
    #pragma unroll
    for (int mt = 0; mt < 2; mt++)
        #pragma unroll
        for (int j = 0; j < 8; j++)
            #pragma unroll
            for (int q = 0; q < 4; q++) acc[mt][j][q] = 0.f;

    load_chunk(0, 0);
    load_chunk(1, 1);

    for (int kt = 0; kt < KT; kt++){
        int b = kt % 3;
        if (kt < KT - 1) { CPWAIT(1); } else { CPWAIT(0); }
        __syncthreads();
        if (kt + 2 < KT) load_chunk(kt + 2, (kt + 2) % 3);

        uint32_t bA = sbase + (uint32_t)b * STAGE;
        uint32_t bB = bA + 16384u;

        #pragma unroll
        for (int ks = 0; ks < 4; ks++){
            uint32_t ko = kx[ks];
            uint32_t fa[2][4], fb[4][4];
            #pragma unroll
            for (int mt = 0; mt < 2; mt++) ldsm4(fa[mt], bA + arow[mt] + ko);
            #pragma unroll
            for (int nt = 0; nt < 4; nt++) ldsm4(fb[nt], bB + brow[nt] + ko);
            #pragma unroll
            for (int mt = 0; mt < 2; mt++){
                #pragma unroll
                for (int j = 0; j < 8; j++){
                    int nt = j >> 1, s = j & 1;
                    hmma(acc[mt][j], fa[mt], fb[nt][s], fb[nt][s+2]);
                }
            }
        }
        __syncthreads();
    }

    // ---- epilogue ----
    int mq = lid >> 2;          // 0..7
    int nq = (lid & 3) * 2;     // 0,2,4,6
    #pragma unroll
    for (int mt = 0; mt < 2; mt++){
        #pragma unroll
        for (int half = 0; half < 2; half++){
            int ml = wm*32 + mt*16 + half*8 + mq;
            if (ml >= cnt) continue;
            int slot = r0 + ml;
            if (MODE == 0){
                size_t orow = (size_t)slot;
                #pragma unroll
                for (int j = 0; j < 8; j++){
                    int ncol = n0 + wn*64 + j*8 + nq;
                    float v0 = acc[mt][j][2*half]   + biasp[ncol];
                    float v1 = acc[mt][j][2*half+1] + biasp[ncol+1];
                    v0 = (v0 > 0.f) ? v0 : 0.01f*v0;
                    v1 = (v1 > 0.f) ? v1 : 0.01f*v1;
                    __half2 hh = __floats2half2_rn(v0, v1);
                    *reinterpret_cast<uint32_t*>(&g_Hh[orow*HID + ncol]) = *reinterpret_cast<uint32_t*>(&hh);
                }
            } else {
                int tok = g_tok[slot];
                float w = g_wslot[slot];
                float* orow = out + (size_t)tok * DIM;
                #pragma unroll
                for (int j = 0; j < 8; j++){
                    int ncol = n0 + wn*64 + j*8 + nq;
                    float v0 = acc[mt][j][2*half]   + biasp[ncol];
                    float v1 = acc[mt][j][2*half+1] + biasp[ncol+1];
                    v0 = (v0 > 0.f) ? v0 : 0.01f*v0;
                    v1 = (v1 > 0.f) ? v1 : 0.01f*v1;
                    atomicAdd(orow + ncol,     w * v0);
                    atomicAdd(orow + ncol + 1, w * v1);
                }
            }
        }
    }
}

// ---------------- launch ----------------
extern "C" void kernel_launch(void* const* d_in, const int* in_sizes, int n_in,
                              void* d_out, int out_size){
    const float* x  = (const float*)d_in[0];
    const float* Wr = (const float*)d_in[1];
    const float* br = (const float*)d_in[2];
    const float* W1 = (const float*)d_in[3];
    const float* b1 = (const float*)d_in[4];
    const float* W2 = (const float*)d_in[5];
    const float* b2 = (const float*)d_in[6];
    float* out = (float*)d_out;

    const int SMEM_DYN = 3*32768;
    cudaFuncSetAttribute(ffn_gemm_mma<0>, cudaFuncAttributeMaxDynamicSharedMemorySize, SMEM_DYN);
    cudaFuncSetAttribute(ffn_gemm_mma<1>, cudaFuncAttributeMaxDynamicSharedMemorySize, SMEM_DYN);

    zero_out_kernel<<<(NTOK*DIM/4)/256, 256>>>(out);
    router_kernel<<<NTOK/8, 256>>>(x, Wr, br);
    finalize_kernel<<<1, 32>>>(out + (out_size - 1));
    scatter_kernel<<<NTOK/256, 256>>>();
    convert_wT_kernel<0><<<dim3(HID/32, DIM/32, NEXP), 256>>>(W1);
    convert_wT_kernel<1><<<dim3(DIM/32, HID/32, NEXP), 256>>>(W2);
    ffn_gemm_mma<0><<<dim3(HID/128, MAXTILES), 256, SMEM_DYN>>>(b1, out);
    ffn_gemm_mma<1><<<dim3(DIM/128, MAXTILES), 256, SMEM_DYN>>>(b2, out);
}